// round 1
// baseline (speedup 1.0000x reference)
#include <cuda_runtime.h>

#define BB 2
#define CC 64
#define CQ 16
#define DD 96
#define PP 9216                    // H*W
#define PDSTRIDE (PP*DD)           // per-channel stride in x: 884736
#define CPD (CC*PDSTRIDE)          // per-batch stride in x
#define PCHUNK 32
#define PCOUT 16

__device__ double g_energy[BB*DD*DD];
__device__ float  g_attn[BB*DD*DD];

// ---------------------------------------------------------------------------
// Kernel A: energy[b,d,e] = sum_{p,cq} (Wq X_p + bq)[cq,d] * (Wk X_p + bk)[cq,e]
// One block handles PCHUNK spatial positions p for one batch b; 96x96 partial
// energy lives in registers (6x6 per thread) and is flushed once via fp64 atomics.
// ---------------------------------------------------------------------------
__global__ void __launch_bounds__(256) energy_k(
    const float* __restrict__ x,
    const float* __restrict__ Wq, const float* __restrict__ bq,
    const float* __restrict__ Wk, const float* __restrict__ bk)
{
    __shared__ float sWq[CQ][CC];
    __shared__ float sWk[CQ][CC];
    __shared__ float sX[CC][DD];
    __shared__ float sQ[CQ][DD];
    __shared__ float sK[CQ][DD];

    const int t  = threadIdx.x;
    const int b  = blockIdx.y;
    const int p0 = blockIdx.x * PCHUNK;

    for (int i = t; i < CQ*CC; i += 256) {
        (&sWq[0][0])[i] = Wq[i];
        (&sWk[0][0])[i] = Wk[i];
    }

    // Q/K compute mapping: thread = (u,v), covers cq in {2u,2u+1}, d in {v, v+32, v+64}
    const int u = t >> 5;     // 0..7
    const int v = t & 31;     // 0..31
    const float bqv[2] = { bq[2*u], bq[2*u+1] };
    const float bkv[2] = { bk[2*u], bk[2*u+1] };

    // Energy accumulate mapping: d = tx+16i, e = ty+16j
    const int tx = t & 15;
    const int ty = t >> 4;

    float acc[6][6];
    #pragma unroll
    for (int i = 0; i < 6; ++i)
        #pragma unroll
        for (int j = 0; j < 6; ++j) acc[i][j] = 0.f;

    const float* xb = x + (size_t)b * CPD;

    for (int pp = 0; pp < PCHUNK; ++pp) {
        const int p = p0 + pp;
        __syncthreads();   // protect sX/sQ/sK from previous iteration's readers

        const float* xp = xb + (size_t)p * DD;
        #pragma unroll
        for (int r = 0; r < (CC*DD)/256; ++r) {
            int i = t + r*256;
            int c = i / DD, d = i - c*DD;
            sX[c][d] = xp[(size_t)c * PDSTRIDE + d];
        }
        __syncthreads();

        // ---- Q,K = W X + b (2cq x 3d tile per thread) ----
        float aq[2][3], ak[2][3];
        #pragma unroll
        for (int i = 0; i < 2; ++i)
            #pragma unroll
            for (int j = 0; j < 3; ++j) { aq[i][j] = bqv[i]; ak[i][j] = bkv[i]; }

        #pragma unroll 8
        for (int c = 0; c < CC; ++c) {
            float xv[3];
            #pragma unroll
            for (int j = 0; j < 3; ++j) xv[j] = sX[c][v + 32*j];
            #pragma unroll
            for (int i = 0; i < 2; ++i) {
                const float wq = sWq[2*u + i][c];
                const float wk = sWk[2*u + i][c];
                #pragma unroll
                for (int j = 0; j < 3; ++j) {
                    aq[i][j] = fmaf(wq, xv[j], aq[i][j]);
                    ak[i][j] = fmaf(wk, xv[j], ak[i][j]);
                }
            }
        }
        #pragma unroll
        for (int i = 0; i < 2; ++i)
            #pragma unroll
            for (int j = 0; j < 3; ++j) {
                sQ[2*u + i][v + 32*j] = aq[i][j];
                sK[2*u + i][v + 32*j] = ak[i][j];
            }
        __syncthreads();

        // ---- energy partial: acc[d,e] += sum_cq Q[cq,d]*K[cq,e] ----
        #pragma unroll 4
        for (int cq = 0; cq < CQ; ++cq) {
            float qv[6], kv[6];
            #pragma unroll
            for (int i = 0; i < 6; ++i) qv[i] = sQ[cq][tx + 16*i];
            #pragma unroll
            for (int j = 0; j < 6; ++j) kv[j] = sK[cq][ty + 16*j];
            #pragma unroll
            for (int i = 0; i < 6; ++i)
                #pragma unroll
                for (int j = 0; j < 6; ++j)
                    acc[i][j] = fmaf(qv[i], kv[j], acc[i][j]);
        }
    }

    const size_t eb = (size_t)b * DD * DD;
    #pragma unroll
    for (int i = 0; i < 6; ++i)
        #pragma unroll
        for (int j = 0; j < 6; ++j)
            atomicAdd(&g_energy[eb + (size_t)(tx + 16*i)*DD + (ty + 16*j)],
                      (double)acc[i][j]);
}

// ---------------------------------------------------------------------------
// Kernel B: row softmax over e. One warp per (b,d) row, 3 elements per lane.
// ---------------------------------------------------------------------------
__global__ void __launch_bounds__(128) softmax_k()
{
    const int w    = (blockIdx.x * blockDim.x + threadIdx.x) >> 5;
    const int lane = threadIdx.x & 31;
    if (w >= BB*DD) return;

    const double* er = g_energy + (size_t)w * DD;
    float v0 = (float)er[lane];
    float v1 = (float)er[lane + 32];
    float v2 = (float)er[lane + 64];

    float m = fmaxf(v0, fmaxf(v1, v2));
    #pragma unroll
    for (int o = 16; o > 0; o >>= 1) m = fmaxf(m, __shfl_xor_sync(0xffffffffu, m, o));

    float e0 = expf(v0 - m), e1 = expf(v1 - m), e2 = expf(v2 - m);
    float s = e0 + e1 + e2;
    #pragma unroll
    for (int o = 16; o > 0; o >>= 1) s += __shfl_xor_sync(0xffffffffu, s, o);

    const float inv = 1.0f / s;
    float* ar = g_attn + (size_t)w * DD;
    ar[lane]      = e0 * inv;
    ar[lane + 32] = e1 * inv;
    ar[lane + 64] = e2 * inv;
}

// ---------------------------------------------------------------------------
// Kernel C: out[b,c,p,d] = gamma*( sum_e (Wv X_p + bv)[c,e] * attn[b,d,e] ) + x
// Wv and attn[b] persist in SMEM across PCOUT spatial positions.
// ---------------------------------------------------------------------------
__global__ void __launch_bounds__(256) out_k(
    const float* __restrict__ x, const float* __restrict__ Wv,
    const float* __restrict__ bv, const float* __restrict__ gamma,
    float* __restrict__ out)
{
    extern __shared__ float sm[];
    float* sWv = sm;                     // 64 x 65 (padded)
    float* sA  = sWv + CC*65;            // 96 x 97 (padded)
    float* sX  = sA  + DD*97;            // 64 x 97 (padded)
    float* sV  = sX  + CC*97;            // 64 x 97 (padded)

    const int t  = threadIdx.x;
    const int b  = blockIdx.y;
    const int p0 = blockIdx.x * PCOUT;
    const int tx = t & 15;
    const int ty = t >> 4;

    for (int i = t; i < CC*CC; i += 256) {
        int c = i >> 6, cc = i & 63;
        sWv[c*65 + cc] = Wv[i];
    }
    for (int i = t; i < DD*DD; i += 256) {
        int d = i / DD, e = i - d*DD;
        sA[d*97 + e] = g_attn[(size_t)b*DD*DD + i];
    }
    const float g = gamma[0];
    float bvv[4];
    #pragma unroll
    for (int k = 0; k < 4; ++k) bvv[k] = bv[ty*4 + k];

    const float* xb = x   + (size_t)b * CPD;
    float*       ob = out + (size_t)b * CPD;

    for (int pp = 0; pp < PCOUT; ++pp) {
        const int p = p0 + pp;
        __syncthreads();   // previous iteration's sX/sV readers done

        const float* xp = xb + (size_t)p * DD;
        #pragma unroll
        for (int r = 0; r < (CC*DD)/256; ++r) {
            int i = t + r*256;
            int c = i / DD, e = i - c*DD;
            sX[c*97 + e] = xp[(size_t)c * PDSTRIDE + e];
        }
        __syncthreads();

        // ---- V = Wv X + bv (4c x 6e tile per thread) ----
        float vv[4][6];
        #pragma unroll
        for (int k = 0; k < 4; ++k)
            #pragma unroll
            for (int j = 0; j < 6; ++j) vv[k][j] = bvv[k];

        #pragma unroll 4
        for (int c2 = 0; c2 < CC; ++c2) {
            float xv[6];
            #pragma unroll
            for (int j = 0; j < 6; ++j) xv[j] = sX[c2*97 + tx + 16*j];
            float wv[4];
            #pragma unroll
            for (int k = 0; k < 4; ++k) wv[k] = sWv[(ty*4 + k)*65 + c2];
            #pragma unroll
            for (int k = 0; k < 4; ++k)
                #pragma unroll
                for (int j = 0; j < 6; ++j)
                    vv[k][j] = fmaf(wv[k], xv[j], vv[k][j]);
        }
        #pragma unroll
        for (int k = 0; k < 4; ++k)
            #pragma unroll
            for (int j = 0; j < 6; ++j)
                sV[(ty*4 + k)*97 + tx + 16*j] = vv[k][j];
        __syncthreads();

        // ---- out tile = V A^T (4c x 6d per thread), fused residual + gamma ----
        float acc[4][6];
        #pragma unroll
        for (int k = 0; k < 4; ++k)
            #pragma unroll
            for (int i = 0; i < 6; ++i) acc[k][i] = 0.f;

        #pragma unroll 4
        for (int e = 0; e < DD; ++e) {
            float av[6];
            #pragma unroll
            for (int i = 0; i < 6; ++i) av[i] = sA[(tx + 16*i)*97 + e];
            float vb[4];
            #pragma unroll
            for (int k = 0; k < 4; ++k) vb[k] = sV[(ty*4 + k)*97 + e];
            #pragma unroll
            for (int k = 0; k < 4; ++k)
                #pragma unroll
                for (int i = 0; i < 6; ++i)
                    acc[k][i] = fmaf(vb[k], av[i], acc[k][i]);
        }

        #pragma unroll
        for (int k = 0; k < 4; ++k) {
            const int c = ty*4 + k;
            #pragma unroll
            for (int i = 0; i < 6; ++i) {
                const int d = tx + 16*i;
                ob[(size_t)c * PDSTRIDE + (size_t)p * DD + d] =
                    g * acc[k][i] + sX[c*97 + d];
            }
        }
    }
}

// ---------------------------------------------------------------------------
extern "C" void kernel_launch(void* const* d_in, const int* in_sizes, int n_in,
                              void* d_out, int out_size)
{
    const float* x  = (const float*)d_in[0];
    const float* Wq = (const float*)d_in[1];
    const float* bq = (const float*)d_in[2];
    const float* Wk = (const float*)d_in[3];
    const float* bk = (const float*)d_in[4];
    const float* Wv = (const float*)d_in[5];
    const float* bv = (const float*)d_in[6];
    const float* gm = (const float*)d_in[7];
    float* out = (float*)d_out;

    void* eptr = nullptr;
    cudaGetSymbolAddress(&eptr, g_energy);
    cudaMemsetAsync(eptr, 0, sizeof(double)*BB*DD*DD, 0);

    energy_k<<<dim3(PP/PCHUNK, BB), 256>>>(x, Wq, bq, Wk, bk);

    softmax_k<<<(BB*DD*32 + 127)/128, 128>>>();

    const size_t smc = (size_t)(CC*65 + DD*97 + CC*97 + CC*97) * sizeof(float);
    cudaFuncSetAttribute(out_k, cudaFuncAttributeMaxDynamicSharedMemorySize, (int)smc);
    out_k<<<dim3(PP/PCOUT, BB), 256, smc>>>(x, Wv, bv, gm, out);
}

// round 3
// speedup vs baseline: 1.2114x; 1.2114x over previous
#include <cuda_runtime.h>

#define BB 2
#define CC 64
#define CQ 16
#define DD 96
#define PP 9216                    // H*W
#define PDSTRIDE (PP*DD)           // per-channel stride in x: 884736
#define CPD (CC*PDSTRIDE)          // per-batch stride in x
#define PCHUNK 32
#define PCOUT 16

typedef unsigned long long u64;

__device__ double g_energy[BB*DD*DD];
__device__ float  g_attn[BB*DD*DD];

// ---- packed f32x2 helpers (FFMA2 path only reachable via PTX) ----
__device__ __forceinline__ u64 pk2(float lo, float hi) {
    u64 r; asm("mov.b64 %0, {%1, %2};" : "=l"(r) : "f"(lo), "f"(hi)); return r;
}
__device__ __forceinline__ u64 bc2(float v) { return pk2(v, v); }
__device__ __forceinline__ void up2(float& lo, float& hi, u64 v) {
    asm("mov.b64 {%0, %1}, %2;" : "=f"(lo), "=f"(hi) : "l"(v));
}
__device__ __forceinline__ u64 ffma2(u64 a, u64 b, u64 c) {
    u64 d; asm("fma.rn.f32x2 %0, %1, %2, %3;" : "=l"(d) : "l"(a), "l"(b), "l"(c));
    return d;
}

// ---------------------------------------------------------------------------
// Kernel A: energy[b,d,e] = sum_{p,cq} (Wq X_p + bq)[cq,d] * (Wk X_p + bk)[cq,e]
// Packed f32x2 everywhere; 96x96 partial energy in registers (6d x 3 e-pairs
// per thread), flushed once via fp64 atomics.
// ---------------------------------------------------------------------------
__global__ void __launch_bounds__(256, 2) energy_k(
    const float* __restrict__ x,
    const float* __restrict__ Wq, const float* __restrict__ bq,
    const float* __restrict__ Wk, const float* __restrict__ bk)
{
    __shared__ __align__(16) float sWq[CQ*CC];
    __shared__ __align__(16) float sWk[CQ*CC];
    __shared__ __align__(16) float sX[CC*DD];
    __shared__ __align__(16) float sQ[CQ*DD];
    __shared__ __align__(16) float sK[CQ*DD];

    const int t  = threadIdx.x;
    const int b  = blockIdx.y;
    const int p0 = blockIdx.x * PCHUNK;

    for (int i = t; i < CQ*CC; i += 256) {
        sWq[i] = Wq[i];
        sWk[i] = Wk[i];
    }

    // QK-compute mapping: 1 cq x 6 consecutive d per thread
    const int cqi = t >> 4;            // 0..15
    const int dxb = 6 * (t & 15);      // d in [dxb, dxb+6)
    const float bq_s = bq[cqi];
    const float bk_s = bk[cqi];

    // accumulate mapping: d = tx+16i (scalar), e = 6*ty + 2j + h (pairs)
    const int tx = t & 15;
    const int ty = t >> 4;

    u64 acc[6][3];
    #pragma unroll
    for (int i = 0; i < 6; ++i)
        #pragma unroll
        for (int j = 0; j < 3; ++j) acc[i][j] = 0ull;

    const float* xb = x + (size_t)b * CPD;

    for (int pp = 0; pp < PCHUNK; ++pp) {
        const int p = p0 + pp;
        __syncthreads();

        // ---- load X slab (64 x 96) as float2, coalesced ----
        const float* xp = xb + (size_t)p * DD;
        #pragma unroll
        for (int r = 0; r < 12; ++r) {
            int i2 = t + r * 256;          // 3072 float2 slots
            int c  = i2 / 48, dp = i2 % 48;
            float2 v = *reinterpret_cast<const float2*>(xp + (size_t)c * PDSTRIDE + 2*dp);
            *reinterpret_cast<float2*>(&sX[c*DD + 2*dp]) = v;
        }
        __syncthreads();

        // ---- Q,K = W X + b  (1 cq x 3 d-pairs per thread) ----
        u64 qa[3], ka[3];
        #pragma unroll
        for (int j = 0; j < 3; ++j) { qa[j] = bc2(bq_s); ka[j] = bc2(bk_s); }

        #pragma unroll 4
        for (int c4 = 0; c4 < CC; c4 += 4) {
            const float4 wq4 = *reinterpret_cast<const float4*>(&sWq[cqi*CC + c4]);
            const float4 wk4 = *reinterpret_cast<const float4*>(&sWk[cqi*CC + c4]);
            const float wq[4] = {wq4.x, wq4.y, wq4.z, wq4.w};
            const float wk[4] = {wk4.x, wk4.y, wk4.z, wk4.w};
            #pragma unroll
            for (int cc = 0; cc < 4; ++cc) {
                const int c = c4 + cc;
                u64 xv[3];
                #pragma unroll
                for (int j = 0; j < 3; ++j)
                    xv[j] = *reinterpret_cast<const u64*>(&sX[c*DD + dxb + 2*j]);
                const u64 wqb = bc2(wq[cc]);
                const u64 wkb = bc2(wk[cc]);
                #pragma unroll
                for (int j = 0; j < 3; ++j) {
                    qa[j] = ffma2(wqb, xv[j], qa[j]);
                    ka[j] = ffma2(wkb, xv[j], ka[j]);
                }
            }
        }
        #pragma unroll
        for (int j = 0; j < 3; ++j) {
            *reinterpret_cast<u64*>(&sQ[cqi*DD + dxb + 2*j]) = qa[j];
            *reinterpret_cast<u64*>(&sK[cqi*DD + dxb + 2*j]) = ka[j];
        }
        __syncthreads();

        // ---- energy partial: acc[d, e-pair] += Q[cq,d] * K[cq, e-pair] ----
        #pragma unroll 2
        for (int cq = 0; cq < CQ; ++cq) {
            u64 kv[3];
            #pragma unroll
            for (int j = 0; j < 3; ++j)
                kv[j] = *reinterpret_cast<const u64*>(&sK[cq*DD + 6*ty + 2*j]);
            #pragma unroll
            for (int i = 0; i < 6; ++i) {
                const u64 qb = bc2(sQ[cq*DD + tx + 16*i]);
                #pragma unroll
                for (int j = 0; j < 3; ++j)
                    acc[i][j] = ffma2(qb, kv[j], acc[i][j]);
            }
        }
    }

    const size_t eb = (size_t)b * DD * DD;
    #pragma unroll
    for (int i = 0; i < 6; ++i)
        #pragma unroll
        for (int j = 0; j < 3; ++j) {
            float lo, hi;
            up2(lo, hi, acc[i][j]);
            const size_t base = eb + (size_t)(tx + 16*i)*DD + (6*ty + 2*j);
            atomicAdd(&g_energy[base],     (double)lo);
            atomicAdd(&g_energy[base + 1], (double)hi);
        }
}

// ---------------------------------------------------------------------------
// Kernel B: row softmax over e. One warp per (b,d) row.
// ---------------------------------------------------------------------------
__global__ void __launch_bounds__(128) softmax_k()
{
    const int w    = (blockIdx.x * blockDim.x + threadIdx.x) >> 5;
    const int lane = threadIdx.x & 31;
    if (w >= BB*DD) return;

    const double* er = g_energy + (size_t)w * DD;
    float v0 = (float)er[lane];
    float v1 = (float)er[lane + 32];
    float v2 = (float)er[lane + 64];

    float m = fmaxf(v0, fmaxf(v1, v2));
    #pragma unroll
    for (int o = 16; o > 0; o >>= 1) m = fmaxf(m, __shfl_xor_sync(0xffffffffu, m, o));

    float e0 = expf(v0 - m), e1 = expf(v1 - m), e2 = expf(v2 - m);
    float s = e0 + e1 + e2;
    #pragma unroll
    for (int o = 16; o > 0; o >>= 1) s += __shfl_xor_sync(0xffffffffu, s, o);

    const float inv = 1.0f / s;
    float* ar = g_attn + (size_t)w * DD;
    ar[lane]      = e0 * inv;
    ar[lane + 32] = e1 * inv;
    ar[lane + 64] = e2 * inv;
}

// ---------------------------------------------------------------------------
// Kernel C: out[b,c,p,d] = gamma*( sum_e (Wv X_p + bv)[c,e] * attn[b,d,e] ) + x
// Attn stored transposed in SMEM (stride 98) so d pairs are contiguous.
// ---------------------------------------------------------------------------
#define ATS 98

__global__ void __launch_bounds__(256, 2) out_k(
    const float* __restrict__ x, const float* __restrict__ Wv,
    const float* __restrict__ bv, const float* __restrict__ gamma,
    float* __restrict__ out)
{
    extern __shared__ __align__(16) float sm[];
    float* sWv = sm;                       // 64 x 64
    float* sAT = sWv + CC*CC;              // 96 x 98  (sAT[e*98 + d])
    float* sX  = sAT + DD*ATS;             // 64 x 96
    float* sV  = sX  + CC*DD;              // 64 x 96

    const int t  = threadIdx.x;
    const int b  = blockIdx.y;
    const int p0 = blockIdx.x * PCOUT;
    const int tx = t & 15;                 // d-group: d = 6*tx + {0..5}
    const int ty = t >> 4;                 // c-group: c = 4*ty + {0..3}
    const int dxb = 6 * tx;

    for (int i = t; i < CC*CC; i += 256) sWv[i] = Wv[i];
    for (int i = t; i < DD*DD; i += 256) {
        int d = i / DD, e = i - d*DD;      // coalesced read of g_attn[b][d][e]
        sAT[e*ATS + d] = g_attn[(size_t)b*DD*DD + i];
    }
    const u64 gbc = bc2(gamma[0]);
    float bvv[4];
    #pragma unroll
    for (int k = 0; k < 4; ++k) bvv[k] = bv[4*ty + k];

    const float* xb = x   + (size_t)b * CPD;
    float*       ob = out + (size_t)b * CPD;

    for (int pp = 0; pp < PCOUT; ++pp) {
        const int p = p0 + pp;
        __syncthreads();

        const float* xp = xb + (size_t)p * DD;
        #pragma unroll
        for (int r = 0; r < 12; ++r) {
            int i2 = t + r * 256;
            int c  = i2 / 48, dp = i2 % 48;
            float2 v = *reinterpret_cast<const float2*>(xp + (size_t)c * PDSTRIDE + 2*dp);
            *reinterpret_cast<float2*>(&sX[c*DD + 2*dp]) = v;
        }
        __syncthreads();

        // ---- V = Wv X + bv  (4 c x 3 e-pairs per thread), 2-c2 batching ----
        u64 vv[4][3];
        #pragma unroll
        for (int k = 0; k < 4; ++k)
            #pragma unroll
            for (int j = 0; j < 3; ++j) vv[k][j] = bc2(bvv[k]);

        #pragma unroll 2
        for (int c2 = 0; c2 < CC; c2 += 2) {
            u64 x0[3], x1[3];
            #pragma unroll
            for (int j = 0; j < 3; ++j) {
                x0[j] = *reinterpret_cast<const u64*>(&sX[c2*DD + dxb + 2*j]);
                x1[j] = *reinterpret_cast<const u64*>(&sX[(c2+1)*DD + dxb + 2*j]);
            }
            #pragma unroll
            for (int k = 0; k < 4; ++k) {
                const u64 w2 = *reinterpret_cast<const u64*>(&sWv[(4*ty + k)*CC + c2]);
                float wlo, whi; up2(wlo, whi, w2);
                const u64 wb0 = bc2(wlo), wb1 = bc2(whi);
                #pragma unroll
                for (int j = 0; j < 3; ++j) {
                    vv[k][j] = ffma2(wb0, x0[j], vv[k][j]);
                    vv[k][j] = ffma2(wb1, x1[j], vv[k][j]);
                }
            }
        }
        #pragma unroll
        for (int k = 0; k < 4; ++k)
            #pragma unroll
            for (int j = 0; j < 3; ++j)
                *reinterpret_cast<u64*>(&sV[(4*ty + k)*DD + dxb + 2*j]) = vv[k][j];
        __syncthreads();

        // ---- out tile = V A^T  (4 c x 3 d-pairs per thread), 2-e batching ----
        u64 acc[4][3];
        #pragma unroll
        for (int k = 0; k < 4; ++k)
            #pragma unroll
            for (int j = 0; j < 3; ++j) acc[k][j] = 0ull;

        #pragma unroll 2
        for (int e = 0; e < DD; e += 2) {
            u64 a0[3], a1[3];
            #pragma unroll
            for (int j = 0; j < 3; ++j) {
                a0[j] = *reinterpret_cast<const u64*>(&sAT[e*ATS + dxb + 2*j]);
                a1[j] = *reinterpret_cast<const u64*>(&sAT[(e+1)*ATS + dxb + 2*j]);
            }
            #pragma unroll
            for (int k = 0; k < 4; ++k) {
                const u64 v2 = *reinterpret_cast<const u64*>(&sV[(4*ty + k)*DD + e]);
                float vlo, vhi; up2(vlo, vhi, v2);
                const u64 vb0 = bc2(vlo), vb1 = bc2(vhi);
                #pragma unroll
                for (int j = 0; j < 3; ++j) {
                    acc[k][j] = ffma2(vb0, a0[j], acc[k][j]);
                    acc[k][j] = ffma2(vb1, a1[j], acc[k][j]);
                }
            }
        }

        // ---- epilogue: out = gamma*acc + x, packed stores ----
        #pragma unroll
        for (int k = 0; k < 4; ++k) {
            const int c = 4*ty + k;
            #pragma unroll
            for (int j = 0; j < 3; ++j) {
                const u64 x2 = *reinterpret_cast<const u64*>(&sX[c*DD + dxb + 2*j]);
                const u64 r  = ffma2(acc[k][j], gbc, x2);
                *reinterpret_cast<u64*>(&ob[(size_t)c * PDSTRIDE + (size_t)p * DD + dxb + 2*j]) = r;
            }
        }
    }
}

// ---------------------------------------------------------------------------
extern "C" void kernel_launch(void* const* d_in, const int* in_sizes, int n_in,
                              void* d_out, int out_size)
{
    const float* x  = (const float*)d_in[0];
    const float* Wq = (const float*)d_in[1];
    const float* bq = (const float*)d_in[2];
    const float* Wk = (const float*)d_in[3];
    const float* bk = (const float*)d_in[4];
    const float* Wv = (const float*)d_in[5];
    const float* bv = (const float*)d_in[6];
    const float* gm = (const float*)d_in[7];
    float* out = (float*)d_out;

    void* eptr = nullptr;
    cudaGetSymbolAddress(&eptr, g_energy);
    cudaMemsetAsync(eptr, 0, sizeof(double)*BB*DD*DD, 0);

    energy_k<<<dim3(PP/PCHUNK, BB), 256>>>(x, Wq, bq, Wk, bk);

    softmax_k<<<(BB*DD*32 + 127)/128, 128>>>();

    const size_t smc = (size_t)(CC*CC + DD*ATS + CC*DD + CC*DD) * sizeof(float);
    cudaFuncSetAttribute(out_k, cudaFuncAttributeMaxDynamicSharedMemorySize, (int)smc);
    out_k<<<dim3(PP/PCOUT, BB), 256, smc>>>(x, Wv, bv, gm, out);
}